// round 9
// baseline (speedup 1.0000x reference)
#include <cuda_runtime.h>

#define B_    4
#define C_    128
#define W_    128
#define H_    128
#define DWIN  21
#define PADN  10
#define KC    2                    // channels per staged chunk
#define NWARP 3                    // di per block; 21 = 7 * 3
#define THREADS (NWARP * 32)       // 96
#define SHIFT  12                  // staged window starts at col -12 (16B aligned)
#define ROWLEN 152                 // cols -12..139 -> 38 float4 groups
#define NG1    (ROWLEN / 4)        // 38
#define NCHUNK (C_ / KC)           // 64

typedef unsigned long long ull;

__device__ __forceinline__ ull ffma2(ull a, ull b, ull c) {
    ull d;
    asm("fma.rn.f32x2 %0, %1, %2, %3;" : "=l"(d) : "l"(a), "l"(b), "l"(c));
    return d;
}
__device__ __forceinline__ ull dup2(float x) {
    ull r;
    unsigned u = __float_as_uint(x);
    asm("mov.b64 %0, {%1, %1};" : "=l"(r) : "r"(u));
    return r;
}
__device__ __forceinline__ float lo2(ull v) { return __uint_as_float((unsigned)v); }
__device__ __forceinline__ float hi2(ull v) { return __uint_as_float((unsigned)(v >> 32)); }

__global__ __launch_bounds__(THREADS, 4)
void corr_kernel(const float* __restrict__ x1,
                 const float* __restrict__ x2,
                 float* __restrict__ out)
{
    __shared__ __align__(16) float s_x1[NWARP][KC][ROWLEN]; // 3*2*152*4 = 3648 B
    __shared__ __align__(16) float s_x2[KC][128];           // 2*128*4   = 1024 B

    const int dig = blockIdx.x;        // 0..6
    const int i   = blockIdx.y;        // 0..127
    const int b   = blockIdx.z;        // 0..3
    const int di0 = dig * NWARP;

    const int tid  = threadIdx.x;
    const int warp = tid >> 5;         // 0..2 -> di = di0 + warp
    const int lane = tid & 31;         // j = 4*lane .. 4*lane+3

    const int row   = i + di0 + warp - PADN;
    const bool rowok = (row >= 0) && (row < W_);

    const float* x1b = x1 + (size_t)b * C_ * W_ * H_;
    const float* x2b = x2 + (size_t)b * C_ * W_ * H_ + (size_t)i * H_;

    // x1 staging: lane owns float4 groups {lane, lane+32} of each channel row
    const int colA  = 4 * lane - SHIFT;
    const int colB  = colA + 128;
    const bool aok  = rowok && (colA >= 0) && (colA < H_);
    const bool bok  = rowok && (lane < NG1 - 32) && (colB >= 0) && (colB < H_);
    const float* rowsrc = x1b + (size_t)row * H_;
    // x2 staging: threads 0..63 own one float4 group
    const bool g2ok = (tid < KC * 32);
    const int  x2c  = tid >> 5;
    const int  x2g  = tid & 31;
    const float* g2src = x2b + (size_t)x2c * (W_ * H_) + 4 * x2g;

    // packed accumulators over dj pairs (mapping in epilogue; verified in R7)
    ull P0[10], P1[10], P2[10], P3[10];
    float S0 = 0.f, S1 = 0.f, S2 = 0.f, S3 = 0.f;
#pragma unroll
    for (int t = 0; t < 10; t++) { P0[t] = 0ull; P1[t] = 0ull; P2[t] = 0ull; P3[t] = 0ull; }

    float4 rA[KC], rB[KC], r2;
    const float4 z4 = make_float4(0.f, 0.f, 0.f, 0.f);

    // ---- prologue: load chunk 0 ----
#pragma unroll
    for (int c = 0; c < KC; c++) {
        rA[c] = aok ? *(const float4*)(rowsrc + (size_t)c * (W_ * H_) + colA) : z4;
        rB[c] = bok ? *(const float4*)(rowsrc + (size_t)c * (W_ * H_) + colB) : z4;
    }
    r2 = g2ok ? *(const float4*)g2src : z4;

    for (int k = 0; k < NCHUNK; k++) {
        __syncthreads();

        // ---- store staged registers (chunk k) into smem ----
#pragma unroll
        for (int c = 0; c < KC; c++) {
            *(float4*)(&s_x1[warp][c][4 * lane]) = rA[c];
            if (lane < NG1 - 32)
                *(float4*)(&s_x1[warp][c][4 * lane + 128]) = rB[c];
        }
        if (g2ok)
            *(float4*)(&s_x2[x2c][4 * x2g]) = r2;
        __syncthreads();

        // ---- prefetch chunk k+1 into registers ----
        if (k + 1 < NCHUNK) {
            const size_t coff = (size_t)(k + 1) * KC * (W_ * H_);
#pragma unroll
            for (int c = 0; c < KC; c++) {
                const float* s = rowsrc + coff + (size_t)c * (W_ * H_);
                rA[c] = aok ? *(const float4*)(s + colA) : z4;
                rB[c] = bok ? *(const float4*)(s + colB) : z4;
            }
            r2 = g2ok ? *(const float4*)(g2src + coff) : z4;
        }

        // ---- compute chunk k with packed FFMA2 (R7-verified mapping) ----
        // w[m] = s_x1[warp][c][4*lane+2+m]; w2[t] = (w[2t], w[2t+1]), 8B aligned.
#pragma unroll
        for (int c = 0; c < KC; c++) {
            const ull* xw = (const ull*)&s_x1[warp][c][4 * lane + 2];
            ull w2[12];
#pragma unroll
            for (int t = 0; t < 12; t++) w2[t] = xw[t];
            const float4 bv = *(const float4*)(&s_x2[c][4 * lane]);
            const ull bx = dup2(bv.x), by = dup2(bv.y), bz = dup2(bv.z), bw = dup2(bv.w);
#pragma unroll
            for (int t = 0; t < 10; t++) {
                P0[t] = ffma2(w2[t],     bx, P0[t]);   // (acc[2t][0],   acc[2t+1][0])
                P1[t] = ffma2(w2[t + 1], by, P1[t]);   // (acc[2t+1][1], acc[2t+2][1])
                P2[t] = ffma2(w2[t + 1], bz, P2[t]);   // (acc[2t][2],   acc[2t+1][2])
                P3[t] = ffma2(w2[t + 2], bw, P3[t]);   // (acc[2t+1][3], acc[2t+2][3])
            }
            S0 += lo2(w2[10]) * bv.x;   // acc[20][0]
            S1 += hi2(w2[0])  * bv.y;   // acc[0][1]
            S2 += lo2(w2[11]) * bv.z;   // acc[20][2]
            S3 += hi2(w2[1])  * bv.w;   // acc[0][3]
        }
    }

    // ---- epilogue: unpack and write out[b, (di0+warp)*21+dj, i, 4*lane..+3] ----
    float acc[DWIN][4];
#pragma unroll
    for (int t = 0; t < 10; t++) {
        acc[2*t][0]   = lo2(P0[t]);  acc[2*t+1][0] = hi2(P0[t]);
        acc[2*t+1][1] = lo2(P1[t]);  acc[2*t+2][1] = hi2(P1[t]);
        acc[2*t][2]   = lo2(P2[t]);  acc[2*t+1][2] = hi2(P2[t]);
        acc[2*t+1][3] = lo2(P3[t]);  acc[2*t+2][3] = hi2(P3[t]);
    }
    acc[20][0] = S0;
    acc[0][1]  = S1;
    acc[20][2] = S2;
    acc[0][3]  = S3;

    const int di = di0 + warp;
    float* ob = out + (((size_t)b * (DWIN * DWIN) + (size_t)di * DWIN) * W_ + i) * H_
                    + 4 * lane;
#pragma unroll
    for (int dj = 0; dj < DWIN; dj++) {
        *(float4*)(ob + (size_t)dj * (W_ * H_)) =
            make_float4(acc[dj][0], acc[dj][1], acc[dj][2], acc[dj][3]);
    }
}

extern "C" void kernel_launch(void* const* d_in, const int* in_sizes, int n_in,
                              void* d_out, int out_size)
{
    const float* x1 = (const float*)d_in[0];
    const float* x2 = (const float*)d_in[1];
    float* out = (float*)d_out;

    dim3 grid(7, W_, B_);   // (dig, i, b)
    corr_kernel<<<grid, THREADS>>>(x1, x2, out);
}

// round 10
// speedup vs baseline: 1.4408x; 1.4408x over previous
#include <cuda_runtime.h>

#define B_    4
#define C_    128
#define W_    128
#define H_    128
#define DWIN  21
#define PADN  10
#define KC    2                    // channels per staged chunk
#define NWARP 3                    // di per block; 21 = 7 * 3
#define THREADS (NWARP * 32)       // 96
#define SHIFT  12                  // staged window starts at col -12 (16B aligned)
#define ROWLEN 152                 // cols -12..139 -> 38 float4 groups
#define NG1    (ROWLEN / 4)        // 38
#define NCHUNK (C_ / KC)           // 64

typedef unsigned long long ull;

__device__ __forceinline__ ull ffma2(ull a, ull b, ull c) {
    ull d;
    asm("fma.rn.f32x2 %0, %1, %2, %3;" : "=l"(d) : "l"(a), "l"(b), "l"(c));
    return d;
}
__device__ __forceinline__ ull dup2(float x) {
    ull r;
    unsigned u = __float_as_uint(x);
    asm("mov.b64 %0, {%1, %1};" : "=l"(r) : "r"(u));
    return r;
}
__device__ __forceinline__ float lo2(ull v) { return __uint_as_float((unsigned)v); }
__device__ __forceinline__ float hi2(ull v) { return __uint_as_float((unsigned)(v >> 32)); }

__global__ __launch_bounds__(THREADS, 4)
void corr_kernel(const float* __restrict__ x1,
                 const float* __restrict__ x2,
                 float* __restrict__ out)
{
    __shared__ __align__(16) float s_x1[NWARP][KC][ROWLEN]; // 3*2*152*4 = 3648 B
    __shared__ __align__(16) float s_x2[KC][128];           // 2*128*4   = 1024 B

    const int dig = blockIdx.x;        // 0..6
    const int i   = blockIdx.y;        // 0..127
    const int b   = blockIdx.z;        // 0..3
    const int di0 = dig * NWARP;

    const int tid  = threadIdx.x;
    const int warp = tid >> 5;         // 0..2 -> di = di0 + warp
    const int lane = tid & 31;         // j = 4*lane .. 4*lane+3

    const int row   = i + di0 + warp - PADN;
    const bool rowok = (row >= 0) && (row < W_);

    const float* x1b = x1 + (size_t)b * C_ * W_ * H_;
    const float* x2b = x2 + (size_t)b * C_ * W_ * H_ + (size_t)i * H_;

    // x1 staging: lane owns float4 groups {lane, lane+32} of each channel row
    const int colA  = 4 * lane - SHIFT;
    const int colB  = colA + 128;
    const bool aok  = rowok && (colA >= 0) && (colA < H_);
    const bool bok  = rowok && (lane < NG1 - 32) && (colB >= 0) && (colB < H_);
    const float* rowsrc = x1b + (size_t)row * H_;
    // x2 staging: threads 0..63 own one float4 group
    const bool g2ok = (tid < KC * 32);
    const int  x2c  = tid >> 5;
    const int  x2g  = tid & 31;
    const float* g2src = x2b + (size_t)x2c * (W_ * H_) + 4 * x2g;

    // packed accumulators over dj pairs (mapping verified in R7/R9)
    ull P0[10], P1[10], P2[10], P3[10];
    float S0 = 0.f, S1 = 0.f, S2 = 0.f, S3 = 0.f;
#pragma unroll
    for (int t = 0; t < 10; t++) { P0[t] = 0ull; P1[t] = 0ull; P2[t] = 0ull; P3[t] = 0ull; }

    float4 rA[KC], rB[KC], r2;
    const float4 z4 = make_float4(0.f, 0.f, 0.f, 0.f);

    // ---- prologue: load chunk 0 ----
#pragma unroll
    for (int c = 0; c < KC; c++) {
        rA[c] = aok ? *(const float4*)(rowsrc + (size_t)c * (W_ * H_) + colA) : z4;
        rB[c] = bok ? *(const float4*)(rowsrc + (size_t)c * (W_ * H_) + colB) : z4;
    }
    r2 = g2ok ? *(const float4*)g2src : z4;

    for (int k = 0; k < NCHUNK; k++) {
        __syncthreads();

        // ---- store staged registers (chunk k) into smem ----
#pragma unroll
        for (int c = 0; c < KC; c++) {
            *(float4*)(&s_x1[warp][c][4 * lane]) = rA[c];
            if (lane < NG1 - 32)
                *(float4*)(&s_x1[warp][c][4 * lane + 128]) = rB[c];
        }
        if (g2ok)
            *(float4*)(&s_x2[x2c][4 * x2g]) = r2;
        __syncthreads();

        // ---- prefetch chunk k+1 into registers ----
        if (k + 1 < NCHUNK) {
            const size_t coff = (size_t)(k + 1) * KC * (W_ * H_);
#pragma unroll
            for (int c = 0; c < KC; c++) {
                const float* s = rowsrc + coff + (size_t)c * (W_ * H_);
                rA[c] = aok ? *(const float4*)(s + colA) : z4;
                rB[c] = bok ? *(const float4*)(s + colB) : z4;
            }
            r2 = g2ok ? *(const float4*)(g2src + coff) : z4;
        }

        // ---- compute chunk k: dense aligned LDS.128 window + packed FFMA2 ----
        // Load staged cols [4*lane, 4*lane+27] as 7 aligned float4 (dense across lanes).
        // Staged col p <-> global col p-12; needed w[m] (global 4*lane-10+m) = W[m+2].
        // ull pairs u[t] = (W[2t], W[2t+1]); old w2[t] == u[t+1].
#pragma unroll
        for (int c = 0; c < KC; c++) {
            const float4* xf = (const float4*)&s_x1[warp][c][4 * lane]; // 16B aligned
            ull u[14];
#pragma unroll
            for (int t = 0; t < 7; t++) {
                const float4 q = xf[t];
                u[2*t]     = ((const ull*)&q)[0];
                u[2*t + 1] = ((const ull*)&q)[1];
            }
            const float4 bv = *(const float4*)(&s_x2[c][4 * lane]);
            const ull bx = dup2(bv.x), by = dup2(bv.y), bz = dup2(bv.z), bw = dup2(bv.w);
#pragma unroll
            for (int t = 0; t < 10; t++) {
                P0[t] = ffma2(u[t + 1], bx, P0[t]);   // (acc[2t][0],   acc[2t+1][0])
                P1[t] = ffma2(u[t + 2], by, P1[t]);   // (acc[2t+1][1], acc[2t+2][1])
                P2[t] = ffma2(u[t + 2], bz, P2[t]);   // (acc[2t][2],   acc[2t+1][2])
                P3[t] = ffma2(u[t + 3], bw, P3[t]);   // (acc[2t+1][3], acc[2t+2][3])
            }
            S0 += lo2(u[11]) * bv.x;   // acc[20][0] += w[20]*bv.x
            S1 += hi2(u[1])  * bv.y;   // acc[0][1]  += w[1] *bv.y
            S2 += lo2(u[12]) * bv.z;   // acc[20][2] += w[22]*bv.z
            S3 += hi2(u[2])  * bv.w;   // acc[0][3]  += w[3] *bv.w
        }
    }

    // ---- epilogue: unpack and write out[b, (di0+warp)*21+dj, i, 4*lane..+3] ----
    float acc[DWIN][4];
#pragma unroll
    for (int t = 0; t < 10; t++) {
        acc[2*t][0]   = lo2(P0[t]);  acc[2*t+1][0] = hi2(P0[t]);
        acc[2*t+1][1] = lo2(P1[t]);  acc[2*t+2][1] = hi2(P1[t]);
        acc[2*t][2]   = lo2(P2[t]);  acc[2*t+1][2] = hi2(P2[t]);
        acc[2*t+1][3] = lo2(P3[t]);  acc[2*t+2][3] = hi2(P3[t]);
    }
    acc[20][0] = S0;
    acc[0][1]  = S1;
    acc[20][2] = S2;
    acc[0][3]  = S3;

    const int di = di0 + warp;
    float* ob = out + (((size_t)b * (DWIN * DWIN) + (size_t)di * DWIN) * W_ + i) * H_
                    + 4 * lane;
#pragma unroll
    for (int dj = 0; dj < DWIN; dj++) {
        *(float4*)(ob + (size_t)dj * (W_ * H_)) =
            make_float4(acc[dj][0], acc[dj][1], acc[dj][2], acc[dj][3]);
    }
}

extern "C" void kernel_launch(void* const* d_in, const int* in_sizes, int n_in,
                              void* d_out, int out_size)
{
    const float* x1 = (const float*)d_in[0];
    const float* x2 = (const float*)d_in[1];
    float* out = (float*)d_out;

    dim3 grid(7, W_, B_);   // (dig, i, b)
    corr_kernel<<<grid, THREADS>>>(x1, x2, out);
}